// round 14
// baseline (speedup 1.0000x reference)
#include <cuda_runtime.h>
#include <cuda_fp16.h>
#include <cstdint>

#define BB 4
#define LL 1024
#define DD 768
#define HH 12
#define DHH 64

// Packed fp16 scratch: XM tiles, k-contiguous, k-chunks of 64.
//   128-row tile = 128 x 72 halfs (64 data + 8 pad) = 18432B
//   64-row tile  =  64 x 72 halfs = 9216B
#define TH128 9216
#define TH64  4608
__device__ __align__(1024) __half g_xp [(size_t)BB * 8 * 12 * TH128];
__device__ __align__(1024) __half g_qp [(size_t)HH * 6 * 12 * TH128];
__device__ __align__(1024) __half g_kp [(size_t)HH * 6 * 12 * TH128];
__device__ __align__(1024) __half g_vp [(size_t)HH * 12 * TH64];
__device__ __align__(1024) __half g_Mp [(size_t)HH * 6 * 12 * TH128];
__device__ __align__(1024) __half g_Ap [(size_t)BB * HH * 8 * 12 * TH128];
__device__ __align__(1024) __half g_Sp [(size_t)BB * HH * 8 * 16 * TH128]; // P = exp(S)
__device__ __align__(1024) __half g_Vtp[(size_t)BB * HH * 16 * TH64];
__device__ float g_rsum[(size_t)BB * HH * LL];            // per-row sums of exp(S)

__device__ __forceinline__ void mma_f16(float* c, const unsigned* a, const unsigned* b) {
    asm volatile(
        "mma.sync.aligned.m16n8k16.row.col.f32.f16.f16.f32 "
        "{%0,%1,%2,%3}, {%4,%5,%6,%7}, {%8,%9}, {%0,%1,%2,%3};"
        : "+f"(c[0]), "+f"(c[1]), "+f"(c[2]), "+f"(c[3])
        : "r"(a[0]), "r"(a[1]), "r"(a[2]), "r"(a[3]), "r"(b[0]), "r"(b[1]));
}

__device__ __forceinline__ uint32_t sa32(const void* p) {
    return (uint32_t)__cvta_generic_to_shared(p);
}
__device__ __forceinline__ void bulk_g2s(uint32_t dst, const void* src,
                                         uint32_t bytes, uint32_t mbar) {
    asm volatile(
        "cp.async.bulk.shared::cluster.global.mbarrier::complete_tx::bytes [%0], [%1], %2, [%3];"
        :: "r"(dst), "l"(src), "r"(bytes), "r"(mbar) : "memory");
}
__device__ __forceinline__ void bar_wait(uint32_t mbar, unsigned parity) {
    asm volatile(
        "{\n\t.reg .pred P;\n\t"
        "W_%=:\n\t"
        "mbarrier.try_wait.parity.acquire.cta.shared::cta.b64 P, [%0], %1, 0x989680;\n\t"
        "@P bra D_%=;\n\t"
        "bra W_%=;\n\t"
        "D_%=:\n\t}"
        :: "r"(mbar), "r"(parity) : "memory");
}
#define MBAR_INIT(a, c) \
    asm volatile("mbarrier.init.shared.b64 [%0], %1;" :: "r"(a), "r"(c) : "memory")
#define MBAR_TX(a, b) \
    asm volatile("mbarrier.arrive.expect_tx.shared.b64 _, [%0], %1;" :: "r"(a), "r"(b) : "memory")
#define MBAR_ARRIVE(a) \
    asm volatile("mbarrier.arrive.release.cta.shared::cta.b64 _, [%0];" :: "r"(a) : "memory")

// ---------------------------------------------------------------------------
// PERSISTENT bulk-fed fp16 HMMA GEMM.  C[m,n] = sum_k A[m,k]*B[n,k].
// One block handles tiles bid, bid+G, ... with a CONTINUOUS 3-stage ring
// (prologue paid once; tile epilogues overlap next tile's loads).
// Tile decode: bx = t%gdx, by = (t/gdx)%gdy, bz = t/(gdx*gdy).
//  EPI: 0 plain fp32 (+(z%HH)*64 col offset); 1 fp16 XM tiles rows=m
//  EXS: store exp(acc) + atomic per-row sums;  SCL: scale by 1/rsum[row]
// ---------------------------------------------------------------------------
template<int AZ, int BZ, int BROWS, int EPI, bool EXS, bool SCL>
__global__ __launch_bounds__(256, 2)
void gemm_p(const __half* __restrict__ Apk, const __half* __restrict__ Bpk,
            void* __restrict__ Cg, float* __restrict__ rsum,
            int nkt, int cNK, long czs, long cs1, int ldc,
            int gdx, int gdy, int ntiles)
{
    constexpr int BTH = BROWS * 72;
    constexpr uint32_t ABYT = TH128 * 2, BBYT = BTH * 2;
    constexpr int STAGE = TH128 + BTH;              // halfs per stage
    constexpr int NT = BROWS / 32;

    extern __shared__ __align__(16) __half smem[];
    const uint32_t mb0 = sa32(&smem[0]);            // full[3]@0,8,16  empty[3]@24,32,40
    __half* tiles = smem + 512;

    const int bid = blockIdx.x;
    const int G = gridDim.x;
    const int cnt = (ntiles - 1 - bid) / G + 1;     // local tile count (bid < ntiles)
    const int TC = cnt * nkt;                       // total local chunks

    const int tid = threadIdx.x;
    const int lane = tid & 31;
    const int wid = tid >> 5;
    const int wm = (wid & 1) * 64;
    const int wn = (wid >> 1) * (BROWS / 4);
    const int lm = lane >> 2;
    const int lk = lane & 3;

    if (tid == 0) {
        MBAR_INIT(mb0, 1);      MBAR_INIT(mb0 + 8, 1);  MBAR_INIT(mb0 + 16, 1);
        MBAR_INIT(mb0 + 24, 8); MBAR_INIT(mb0 + 32, 8); MBAR_INIT(mb0 + 40, 8);
    }
    __syncthreads();

    // issue chunk c (global local-chunk index)
    auto issue = [&](int c) {
        const int st = c % 3;
        const int j = c / nkt, kc = c % nkt;
        const int t = bid + j * G;
        const int bx = t % gdx, by = (t / gdx) % gdy, bz = t / (gdx * gdy);
        const long zA = (AZ == 1) ? bz / HH : (AZ == 2 ? bz % HH : bz);
        const long zB = (BZ == 1) ? bz / HH : (BZ == 2 ? bz % HH : bz);
        const __half* As = Apk + ((zA * gdy + by) * (long)nkt + kc) * TH128;
        const __half* Bs = Bpk + ((zB * gdx + bx) * (long)nkt + kc) * BTH;
        const uint32_t m = mb0 + 8 * st;
        MBAR_TX(m, ABYT + BBYT);
        bulk_g2s(sa32(tiles) + st * STAGE * 2, As, ABYT, m);
        bulk_g2s(sa32(tiles) + st * STAGE * 2 + ABYT, Bs, BBYT, m);
    };
    if (tid == 0) { issue(0); issue(1); issue(2); }

    auto compute = [&](int st, float (*acc)[NT][4]) {
        const __half* __restrict__ Ab = tiles + st * STAGE;
        const __half* __restrict__ Bb = Ab + TH128;
        #pragma unroll
        for (int s = 0; s < 4; s++) {               // 4 x k16 per 64-k stage
            const int kb = s * 16 + 2 * lk;
            unsigned a[4][4], b[NT][2];
            #pragma unroll
            for (int mt = 0; mt < 4; mt++) {
                const int mr = wm + mt * 16 + lm;
                a[mt][0] = *(const unsigned*)&Ab[mr * 72 + kb];
                a[mt][1] = *(const unsigned*)&Ab[(mr + 8) * 72 + kb];
                a[mt][2] = *(const unsigned*)&Ab[mr * 72 + kb + 8];
                a[mt][3] = *(const unsigned*)&Ab[(mr + 8) * 72 + kb + 8];
            }
            #pragma unroll
            for (int nt = 0; nt < NT; nt++) {
                const int nc = wn + nt * 8 + lm;
                b[nt][0] = *(const unsigned*)&Bb[nc * 72 + kb];
                b[nt][1] = *(const unsigned*)&Bb[nc * 72 + kb + 8];
            }
            #pragma unroll
            for (int mt = 0; mt < 4; mt++)
                #pragma unroll
                for (int nt = 0; nt < NT; nt++)
                    mma_f16(acc[mt][nt], a[mt], b[nt]);
        }
    };

    unsigned phF[3] = {0, 0, 0};
    unsigned phE[3] = {0, 0, 0};
    int c = 0;
    for (int j = 0; j < cnt; j++) {
        float acc[4][NT][4];
        #pragma unroll
        for (int i = 0; i < 4; i++)
            #pragma unroll
            for (int jj = 0; jj < NT; jj++)
                #pragma unroll
                for (int r = 0; r < 4; r++) acc[i][jj][r] = 0.f;

        for (int kc = 0; kc < nkt; kc++, c++) {
            const int st = c % 3;
            bar_wait(mb0 + 8 * st, phF[st]);
            phF[st] ^= 1;
            compute(st, acc);
            if (lane == 0) MBAR_ARRIVE(mb0 + 24 + 8 * st);
            if (tid == 0 && c + 3 < TC) {
                bar_wait(mb0 + 24 + 8 * st, phE[st]);
                phE[st] ^= 1;
                issue(c + 3);
            }
        }

        // ---- epilogue for tile j (overlaps next tile's in-flight loads) ----
        const int t = bid + j * G;
        const int bx = t % gdx, by = (t / gdx) % gdy, z = t / (gdx * gdy);
        const int m0 = by * 128;
        const int n0 = bx * BROWS;
        #pragma unroll
        for (int mt = 0; mt < 4; mt++) {
            const int rl = wm + mt * 16 + lm;
            const int rg = m0 + rl;
            float s0 = 0.f, s1 = 0.f;
            float i0 = 1.f, i1 = 1.f;
            if (SCL) {
                i0 = 1.0f / rsum[(long)z * LL + rg];
                i1 = 1.0f / rsum[(long)z * LL + rg + 8];
            }
            #pragma unroll
            for (int nt = 0; nt < NT; nt++) {
                const int cl = wn + nt * 8 + 2 * lk;
                const int cg = n0 + cl;
                float v0 = acc[mt][nt][0], v1 = acc[mt][nt][1];
                float v2 = acc[mt][nt][2], v3 = acc[mt][nt][3];
                if (SCL) { v0 *= i0; v1 *= i0; v2 *= i1; v3 *= i1; }
                if (EPI == 0) {
                    float* C = (float*)Cg + (long)(z / HH) * cs1 + (long)(z % HH) * 64;
                    *(float2*)&C[(long)rg * ldc + cg]       = make_float2(v0, v1);
                    *(float2*)&C[(long)(rg + 8) * ldc + cg] = make_float2(v2, v3);
                } else {
                    __half* zb = (__half*)Cg + (long)z * czs
                               + ((long)by * cNK + (cg >> 6)) * TH128;
                    const int co = cl & 63;
                    __half2 h01, h23;
                    if (EXS) {
                        h01 = __float22half2_rn(make_float2(__expf(v0), __expf(v1)));
                        h23 = __float22half2_rn(make_float2(__expf(v2), __expf(v3)));
                        const float2 f01 = __half22float2(h01);
                        const float2 f23 = __half22float2(h23);
                        s0 += f01.x + f01.y;
                        s1 += f23.x + f23.y;
                    } else {
                        h01 = __float22half2_rn(make_float2(v0, v1));
                        h23 = __float22half2_rn(make_float2(v2, v3));
                    }
                    *(__half2*)&zb[rl * 72 + co]       = h01;
                    *(__half2*)&zb[(rl + 8) * 72 + co] = h23;
                }
            }
            if (EXS) {
                s0 += __shfl_xor_sync(~0u, s0, 1); s0 += __shfl_xor_sync(~0u, s0, 2);
                s1 += __shfl_xor_sync(~0u, s1, 1); s1 += __shfl_xor_sync(~0u, s1, 2);
                if (lk == 0) {
                    atomicAdd(&rsum[(long)z * LL + rg], s0);
                    atomicAdd(&rsum[(long)z * LL + rg + 8], s1);
                }
            }
        }
    }
}

// ---------------------------------------------------------------------------
// Non-persistent GEMM body for the small fused G1+G5 launch (round-11 code).
//  EPI 2: fp16 XM tiles rows=n (ETR rows/tile, transposed store)
// ---------------------------------------------------------------------------
template<int AZ, int BZ, int BROWS, int ETR>
__device__ __forceinline__
void gemm_dev2(const __half* __restrict__ Apk, const __half* __restrict__ Bpk,
               void* __restrict__ Cg, int nkt, int cNK, long czs,
               int bx, int by, int bz, int gdx, int gdy, __half* smem)
{
    constexpr int BTH = BROWS * 72;
    constexpr uint32_t ABYT = TH128 * 2, BBYT = BTH * 2;
    constexpr int STAGE = TH128 + BTH;
    constexpr int NT = BROWS / 32;

    const uint32_t mb0 = sa32(&smem[0]);
    __half* tiles = smem + 512;

    const int z = bz;
    const long zA = (AZ == 1) ? z / HH : (AZ == 2 ? z % HH : z);
    const long zB = (BZ == 1) ? z / HH : (BZ == 2 ? z % HH : z);
    const __half* Abase = Apk + ((zA * gdy + by) * (long)nkt) * TH128;
    const __half* Bbase = Bpk + ((zB * gdx + bx) * (long)nkt) * BTH;

    const int tid = threadIdx.x;
    const int lane = tid & 31;
    const int wid = tid >> 5;
    const int wm = (wid & 1) * 64;
    const int wn = (wid >> 1) * (BROWS / 4);
    const int lm = lane >> 2;
    const int lk = lane & 3;
    const int m0 = by * 128;
    const int n0 = bx * BROWS;

    float acc[4][NT][4];
    #pragma unroll
    for (int i = 0; i < 4; i++)
        #pragma unroll
        for (int j = 0; j < NT; j++)
            #pragma unroll
            for (int r = 0; r < 4; r++) acc[i][j][r] = 0.f;

    if (tid == 0) {
        MBAR_INIT(mb0, 1);      MBAR_INIT(mb0 + 8, 1);  MBAR_INIT(mb0 + 16, 1);
        MBAR_INIT(mb0 + 24, 8); MBAR_INIT(mb0 + 32, 8); MBAR_INIT(mb0 + 40, 8);
    }
    __syncthreads();

    auto issue = [&](int st, int kt) {
        const uint32_t m = mb0 + 8 * st;
        MBAR_TX(m, ABYT + BBYT);
        bulk_g2s(sa32(tiles) + st * STAGE * 2, Abase + (long)kt * TH128, ABYT, m);
        bulk_g2s(sa32(tiles) + st * STAGE * 2 + ABYT, Bbase + (long)kt * BTH, BBYT, m);
    };
    if (tid == 0) { issue(0, 0); issue(1, 1); issue(2, 2); }

    unsigned phF[3] = {0, 0, 0};
    unsigned phE[3] = {0, 0, 0};
    int st = 0;
    for (int t = 0; t < nkt; t++) {
        bar_wait(mb0 + 8 * st, phF[st]);
        phF[st] ^= 1;
        {
            const __half* __restrict__ Ab = tiles + st * STAGE;
            const __half* __restrict__ Bb = Ab + TH128;
            #pragma unroll
            for (int s = 0; s < 4; s++) {
                const int kb = s * 16 + 2 * lk;
                unsigned a[4][4], b[NT][2];
                #pragma unroll
                for (int mt = 0; mt < 4; mt++) {
                    const int mr = wm + mt * 16 + lm;
                    a[mt][0] = *(const unsigned*)&Ab[mr * 72 + kb];
                    a[mt][1] = *(const unsigned*)&Ab[(mr + 8) * 72 + kb];
                    a[mt][2] = *(const unsigned*)&Ab[mr * 72 + kb + 8];
                    a[mt][3] = *(const unsigned*)&Ab[(mr + 8) * 72 + kb + 8];
                }
                #pragma unroll
                for (int nt = 0; nt < NT; nt++) {
                    const int nc = wn + nt * 8 + lm;
                    b[nt][0] = *(const unsigned*)&Bb[nc * 72 + kb];
                    b[nt][1] = *(const unsigned*)&Bb[nc * 72 + kb + 8];
                }
                #pragma unroll
                for (int mt = 0; mt < 4; mt++)
                    #pragma unroll
                    for (int nt = 0; nt < NT; nt++)
                        mma_f16(acc[mt][nt], a[mt], b[nt]);
            }
        }
        if (lane == 0) MBAR_ARRIVE(mb0 + 24 + 8 * st);
        if (tid == 0 && t + 3 < nkt) {
            bar_wait(mb0 + 24 + 8 * st, phE[st]);
            phE[st] ^= 1;
            issue(st, t + 3);
        }
        st = (st == 2) ? 0 : st + 1;
    }

    #pragma unroll
    for (int mt = 0; mt < 4; mt++) {
        const int rl = wm + mt * 16 + lm;
        const int rg = m0 + rl;
        #pragma unroll
        for (int nt = 0; nt < NT; nt++) {
            const int cl = wn + nt * 8 + 2 * lk;
            const int cg = n0 + cl;
            const float v0 = acc[mt][nt][0], v1 = acc[mt][nt][1];
            const float v2 = acc[mt][nt][2], v3 = acc[mt][nt][3];
            __half* zb = (__half*)Cg + (long)z * czs
                       + ((long)(cg / ETR) * cNK + (rg >> 6)) * (ETR * 72);
            const int rr = rg & 63;
            zb[(cg & (ETR - 1)) * 72 + rr]           = __float2half_rn(v0);
            zb[((cg + 1) & (ETR - 1)) * 72 + rr]     = __float2half_rn(v1);
            zb[(cg & (ETR - 1)) * 72 + rr + 8]       = __float2half_rn(v2);
            zb[((cg + 1) & (ETR - 1)) * 72 + rr + 8] = __float2half_rn(v3);
        }
    }
}

// ---- fused G1 (M^T = q^T k) + G5 (Vt = x v^T) in one launch ---------------
__global__ __launch_bounds__(256, 2)
void gemm_g1g5(const __half* __restrict__ qp, const __half* __restrict__ kp,
               __half* __restrict__ Mp,
               const __half* __restrict__ xp, const __half* __restrict__ vp,
               __half* __restrict__ Vtp)
{
    extern __shared__ __align__(16) __half smem[];
    const int bid = blockIdx.x;
    if (bid < 432) {                                // G1: grid (6,6,12)
        gemm_dev2<0, 0, 128, 128>(qp, kp, Mp, 12, 12, 6L * 12 * TH128,
            bid % 6, (bid / 6) % 6, bid / 36, 6, 6, smem);
    } else {                                        // G5: grid (1,8,48)
        const int t = bid - 432;
        gemm_dev2<1, 2, 64, 64>(xp, vp, Vtp, 12, 16, 16L * TH64,
            0, t % 8, t / 8, 1, 8, smem);
    }
}

// ---------------------------------------------------------------------------
// Fused pack kernel: input packing + rsum zeroing in one launch.
// ---------------------------------------------------------------------------
__device__ __forceinline__
void pack_x_dev(const float* __restrict__ x, __half* __restrict__ xp,
                int kx, int ly, int bz) {
    __half* blob = xp + (((long)bz * 8 + ly) * 12 + kx) * TH128;
    const float* src = x + ((long)(bz * LL + ly * 128)) * DD + kx * 64;
    #pragma unroll
    for (int i = 0; i < 8; i++) {
        const int s = threadIdx.x + i * 256;
        const int row = s >> 4, c4 = (s & 15) << 2;
        const float4 v = *(const float4*)&src[(long)row * DD + c4];
        *(__half2*)&blob[row * 72 + c4]     = __float22half2_rn(make_float2(v.x, v.y));
        *(__half2*)&blob[row * 72 + c4 + 2] = __float22half2_rn(make_float2(v.z, v.w));
    }
}
__device__ __forceinline__
void pack_qk_dev(const float* __restrict__ in, __half* __restrict__ op,
                 int kx, int xy, int hz) {
    __half* blob = op + (((long)hz * 6 + xy) * 12 + kx) * TH128;
    const float* src = in + ((long)hz * DD + kx * 64) * DD + xy * 128;
    #pragma unroll
    for (int i = 0; i < 8; i++) {
        const int s = threadIdx.x + i * 256;
        const int c = s >> 5, x0 = (s & 31) << 2;
        const float4 v = *(const float4*)&src[(long)c * DD + x0];
        blob[(x0 + 0) * 72 + c] = __float2half_rn(v.x);
        blob[(x0 + 1) * 72 + c] = __float2half_rn(v.y);
        blob[(x0 + 2) * 72 + c] = __float2half_rn(v.z);
        blob[(x0 + 3) * 72 + c] = __float2half_rn(v.w);
    }
}
__device__ __forceinline__
void pack_v_dev(const float* __restrict__ v, __half* __restrict__ vp,
                int kx, int hy) {
    __half* blob = vp + ((long)hy * 12 + kx) * TH64;
    const float* src = v + (long)hy * DHH * DD + kx * 64;
    #pragma unroll
    for (int i = 0; i < 4; i++) {
        const int s = threadIdx.x + i * 256;
        const int row = s >> 4, c4 = (s & 15) << 2;
        const float4 w = *(const float4*)&src[(long)row * DD + c4];
        *(__half2*)&blob[row * 72 + c4]     = __float22half2_rn(make_float2(w.x, w.y));
        *(__half2*)&blob[row * 72 + c4 + 2] = __float22half2_rn(make_float2(w.z, w.w));
    }
}

__global__ void pack_all(const float* __restrict__ x, const float* __restrict__ q,
                         const float* __restrict__ k, const float* __restrict__ v,
                         __half* __restrict__ xp, __half* __restrict__ qp,
                         __half* __restrict__ kp, __half* __restrict__ vp,
                         float* __restrict__ rsum)
{
    const int bid = blockIdx.x;
    if (bid < 384) {
        pack_x_dev(x, xp, bid % 12, (bid / 12) % 8, bid / 96);
    } else if (bid < 1248) {
        const int t = bid - 384;
        pack_qk_dev(q, qp, t % 12, (t / 12) % 6, t / 72);
    } else if (bid < 2112) {
        const int t = bid - 1248;
        pack_qk_dev(k, kp, t % 12, (t / 12) % 6, t / 72);
    } else if (bid < 2256) {
        const int t = bid - 2112;
        pack_v_dev(v, vp, t % 12, t / 12);
    } else {
        const int t = bid - 2256;                   // zero rsum: 48 x 1024 floats
        float4* dst = (float4*)&rsum[(long)t * LL];
        dst[threadIdx.x] = make_float4(0.f, 0.f, 0.f, 0.f);
    }
}

// ---------------------------------------------------------------------------
extern "C" void kernel_launch(void* const* d_in, const int* in_sizes, int n_in,
                              void* d_out, int out_size)
{
    const float* x = (const float*)d_in[0];
    const float* k = (const float*)d_in[1];
    const float* q = (const float*)d_in[2];
    const float* v = (const float*)d_in[3];
    float* out = (float*)d_out;

    __half *xp, *qp, *kp, *vp, *Mp, *Ap, *Sp, *Vtp;
    float* rs;
    cudaGetSymbolAddress((void**)&xp, g_xp);
    cudaGetSymbolAddress((void**)&qp, g_qp);
    cudaGetSymbolAddress((void**)&kp, g_kp);
    cudaGetSymbolAddress((void**)&vp, g_vp);
    cudaGetSymbolAddress((void**)&Mp, g_Mp);
    cudaGetSymbolAddress((void**)&Ap, g_Ap);
    cudaGetSymbolAddress((void**)&Sp, g_Sp);
    cudaGetSymbolAddress((void**)&Vtp, g_Vtp);
    cudaGetSymbolAddress((void**)&rs, g_rsum);

    const int SM128 = 1024 + 3 * (18432 + 18432);   // 111616
    const int SM64  = 1024 + 3 * (18432 + 9216);    // 83968
    const int GP = 296;                             // 2 CTAs/SM x 148 SMs

    auto* G2 = gemm_p<1, 2, 128, 1, false, false>;
    auto* G3 = gemm_p<0, 1, 128, 1, true, false>;
    auto* G6 = gemm_p<0, 0, 64, 0, false, true>;
    cudaFuncSetAttribute(gemm_g1g5, cudaFuncAttributeMaxDynamicSharedMemorySize, SM128);
    cudaFuncSetAttribute(G2, cudaFuncAttributeMaxDynamicSharedMemorySize, SM128);
    cudaFuncSetAttribute(G3, cudaFuncAttributeMaxDynamicSharedMemorySize, SM128);
    cudaFuncSetAttribute(G6, cudaFuncAttributeMaxDynamicSharedMemorySize, SM64);

    // 0) pack inputs + zero rsum, one launch
    pack_all<<<dim3(2304), 256>>>(x, q, k, v, xp, qp, kp, vp, rs);

    // 1+5) M^T = q^T k  and  Vt = x v^T, one launch
    gemm_g1g5<<<dim3(816), 256, SM128>>>(qp, kp, Mp, xp, vp, Vtp);

    // 2) A[l,e] = sum_d x[l,d] M^T[e,d]   (persistent, 2304 tiles: gdx=6,gdy=8)
    G2<<<dim3(GP), 256, SM128>>>(xp, Mp, Ap, rs, 12, 12, 8L * 12 * TH128, 0, 0,
                                 6, 8, 2304);

    // 3) P[l,m] = exp(sum_e A[l,e] x[m,e]); rsum atomic  (3072 tiles: 8x8x48)
    G3<<<dim3(GP), 256, SM128>>>(Ap, xp, Sp, rs, 12, 16, 8L * 16 * TH128, 0, 0,
                                 8, 8, 3072);

    // 6) out = (P . Vt) / rsum           (persistent, 384 tiles: 1x8x48)
    G6<<<dim3(GP), 256, SM64>>>(Sp, Vtp, out, rs, 16, 0, 0, (long)LL * DD, DD,
                                1, 8, 384);
}

// round 15
// speedup vs baseline: 1.0890x; 1.0890x over previous
#include <cuda_runtime.h>
#include <cuda_fp16.h>
#include <cstdint>

#define BB 4
#define LL 1024
#define DD 768
#define HH 12
#define DHH 64

// Packed fp16 scratch: XM tiles, k-contiguous, k-chunks of 64.
//   128-row tile = 128 x 72 halfs (64 data + 8 pad) = 18432B
//   64-row tile  =  64 x 72 halfs = 9216B
#define TH128 9216
#define TH64  4608
__device__ __align__(1024) __half g_xp [(size_t)BB * 8 * 12 * TH128];
__device__ __align__(1024) __half g_qp [(size_t)HH * 6 * 12 * TH128];
__device__ __align__(1024) __half g_kp [(size_t)HH * 6 * 12 * TH128];
__device__ __align__(1024) __half g_vp [(size_t)HH * 12 * TH64];
__device__ __align__(1024) __half g_Mp [(size_t)HH * 6 * 12 * TH128];
__device__ __align__(1024) __half g_Ap [(size_t)BB * HH * 8 * 12 * TH128];
__device__ __align__(1024) __half g_Sp [(size_t)BB * HH * 8 * 16 * TH128]; // P = exp(S)
__device__ __align__(1024) __half g_Vtp[(size_t)BB * HH * 16 * TH64];
__device__ float g_rsum[(size_t)BB * HH * LL];       // per-row sums of exp(S)

__device__ __forceinline__ void mma_f16(float* c, const unsigned* a, const unsigned* b) {
    asm volatile(
        "mma.sync.aligned.m16n8k16.row.col.f32.f16.f16.f32 "
        "{%0,%1,%2,%3}, {%4,%5,%6,%7}, {%8,%9}, {%0,%1,%2,%3};"
        : "+f"(c[0]), "+f"(c[1]), "+f"(c[2]), "+f"(c[3])
        : "r"(a[0]), "r"(a[1]), "r"(a[2]), "r"(a[3]), "r"(b[0]), "r"(b[1]));
}

__device__ __forceinline__ uint32_t sa32(const void* p) {
    return (uint32_t)__cvta_generic_to_shared(p);
}
__device__ __forceinline__ void bulk_g2s(uint32_t dst, const void* src,
                                         uint32_t bytes, uint32_t mbar) {
    asm volatile(
        "cp.async.bulk.shared::cluster.global.mbarrier::complete_tx::bytes [%0], [%1], %2, [%3];"
        :: "r"(dst), "l"(src), "r"(bytes), "r"(mbar) : "memory");
}
__device__ __forceinline__ void bar_wait(uint32_t mbar, unsigned parity) {
    asm volatile(
        "{\n\t.reg .pred P;\n\t"
        "W_%=:\n\t"
        "mbarrier.try_wait.parity.acquire.cta.shared::cta.b64 P, [%0], %1, 0x989680;\n\t"
        "@P bra D_%=;\n\t"
        "bra W_%=;\n\t"
        "D_%=:\n\t}"
        :: "r"(mbar), "r"(parity) : "memory");
}
#define MBAR_INIT(a, c) \
    asm volatile("mbarrier.init.shared.b64 [%0], %1;" :: "r"(a), "r"(c) : "memory")
#define MBAR_TX(a, b) \
    asm volatile("mbarrier.arrive.expect_tx.shared.b64 _, [%0], %1;" :: "r"(a), "r"(b) : "memory")
#define MBAR_ARRIVE(a) \
    asm volatile("mbarrier.arrive.release.cta.shared::cta.b64 _, [%0];" :: "r"(a) : "memory")

// ---------------------------------------------------------------------------
// Bulk-fed fp16 HMMA GEMM on packed XM tiles, 3-stage ring with per-warp
// empty barriers.  C[m,n] = sum_k A[m,k]*B[n,k].  Block 128 x BROWS x 64.
//  EPI: 0 plain fp32 (+(z%HH)*64 col offset); 1 fp16 XM tiles rows=m;
//       2 fp16 XM tiles rows=n (ETR rows/tile, transposed store)
//  EXS: epilogue stores exp(acc) via h2exp, accumulates per-row sums
//  SCL: epilogue scales acc by 1/rsum[row]
// ---------------------------------------------------------------------------
template<int AZ, int BZ, int BROWS, int EPI, int ETR, bool EXS, bool SCL>
__device__ __forceinline__
void gemm_dev(const __half* __restrict__ Apk, const __half* __restrict__ Bpk,
              void* __restrict__ Cg, float* __restrict__ rsum,
              int nkt, int cNK, long czs, long cs1, int ldc,
              int bx, int by, int bz, int gdx, int gdy, __half* smem)
{
    constexpr int BTH = BROWS * 72;
    constexpr uint32_t ABYT = TH128 * 2, BBYT = BTH * 2;
    constexpr int STAGE = TH128 + BTH;              // halfs per stage
    constexpr int NT = BROWS / 32;

    const uint32_t mb0 = sa32(&smem[0]);            // full[3] @ +0,8,16; empty[3] @ +24,32,40
    __half* tiles = smem + 512;

    const int z = bz;
    const long zA = (AZ == 1) ? z / HH : (AZ == 2 ? z % HH : z);
    const long zB = (BZ == 1) ? z / HH : (BZ == 2 ? z % HH : z);
    const __half* Abase = Apk + ((zA * gdy + by) * (long)nkt) * TH128;
    const __half* Bbase = Bpk + ((zB * gdx + bx) * (long)nkt) * BTH;

    const int tid = threadIdx.x;
    const int lane = tid & 31;
    const int wid = tid >> 5;
    const int wm = (wid & 1) * 64;
    const int wn = (wid >> 1) * (BROWS / 4);
    const int lm = lane >> 2;
    const int lk = lane & 3;
    const int m0 = by * 128;
    const int n0 = bx * BROWS;

    float acc[4][NT][4];
    #pragma unroll
    for (int i = 0; i < 4; i++)
        #pragma unroll
        for (int j = 0; j < NT; j++)
            #pragma unroll
            for (int r = 0; r < 4; r++) acc[i][j][r] = 0.f;

    if (tid == 0) {
        MBAR_INIT(mb0, 1);      MBAR_INIT(mb0 + 8, 1);  MBAR_INIT(mb0 + 16, 1);
        MBAR_INIT(mb0 + 24, 8); MBAR_INIT(mb0 + 32, 8); MBAR_INIT(mb0 + 40, 8);
    }
    __syncthreads();

    auto issue = [&](int st, int kt) {
        const uint32_t m = mb0 + 8 * st;
        MBAR_TX(m, ABYT + BBYT);
        bulk_g2s(sa32(tiles) + st * STAGE * 2, Abase + (long)kt * TH128, ABYT, m);
        bulk_g2s(sa32(tiles) + st * STAGE * 2 + ABYT, Bbase + (long)kt * BTH, BBYT, m);
    };
    if (tid == 0) { issue(0, 0); issue(1, 1); issue(2, 2); }

    auto compute = [&](int st) {
        const __half* __restrict__ Ab = tiles + st * STAGE;
        const __half* __restrict__ Bb = Ab + TH128;
        #pragma unroll
        for (int s = 0; s < 4; s++) {               // 4 x k16 per 64-k stage
            const int kb = s * 16 + 2 * lk;
            unsigned a[4][4], b[NT][2];
            #pragma unroll
            for (int mt = 0; mt < 4; mt++) {
                const int mr = wm + mt * 16 + lm;
                a[mt][0] = *(const unsigned*)&Ab[mr * 72 + kb];
                a[mt][1] = *(const unsigned*)&Ab[(mr + 8) * 72 + kb];
                a[mt][2] = *(const unsigned*)&Ab[mr * 72 + kb + 8];
                a[mt][3] = *(const unsigned*)&Ab[(mr + 8) * 72 + kb + 8];
            }
            #pragma unroll
            for (int nt = 0; nt < NT; nt++) {
                const int nc = wn + nt * 8 + lm;
                b[nt][0] = *(const unsigned*)&Bb[nc * 72 + kb];
                b[nt][1] = *(const unsigned*)&Bb[nc * 72 + kb + 8];
            }
            #pragma unroll
            for (int mt = 0; mt < 4; mt++)
                #pragma unroll
                for (int nt = 0; nt < NT; nt++)
                    mma_f16(acc[mt][nt], a[mt], b[nt]);
        }
    };

    unsigned phF[3] = {0, 0, 0};
    unsigned phE[3] = {0, 0, 0};
    int st = 0;
    for (int t = 0; t < nkt; t++) {
        bar_wait(mb0 + 8 * st, phF[st]);
        phF[st] ^= 1;
        compute(st);
        if (lane == 0) MBAR_ARRIVE(mb0 + 24 + 8 * st);     // warp done with stage
        if (tid == 0 && t + 3 < nkt) {
            bar_wait(mb0 + 24 + 8 * st, phE[st]);          // all 8 warps done
            phE[st] ^= 1;
            issue(st, t + 3);
        }
        st = (st == 2) ? 0 : st + 1;
    }

    // ---- epilogue ----
    #pragma unroll
    for (int mt = 0; mt < 4; mt++) {
        const int rl = wm + mt * 16 + lm;
        const int rg = m0 + rl;
        float s0 = 0.f, s1 = 0.f;
        float i0 = 1.f, i1 = 1.f;
        if (SCL) {
            i0 = 1.0f / rsum[(long)z * LL + rg];
            i1 = 1.0f / rsum[(long)z * LL + rg + 8];
        }
        #pragma unroll
        for (int nt = 0; nt < NT; nt++) {
            const int cl = wn + nt * 8 + 2 * lk;
            const int cg = n0 + cl;
            float v0 = acc[mt][nt][0], v1 = acc[mt][nt][1];
            float v2 = acc[mt][nt][2], v3 = acc[mt][nt][3];
            if (SCL) { v0 *= i0; v1 *= i0; v2 *= i1; v3 *= i1; }
            if (EPI == 0) {
                float* C = (float*)Cg + (long)(z / HH) * cs1 + (long)(z % HH) * 64;
                *(float2*)&C[(long)rg * ldc + cg]       = make_float2(v0, v1);
                *(float2*)&C[(long)(rg + 8) * ldc + cg] = make_float2(v2, v3);
            } else if (EPI == 1) {
                __half* zb = (__half*)Cg + (long)z * czs
                           + ((long)by * cNK + (cg >> 6)) * TH128;
                const int co = cl & 63;
                __half2 h01, h23;
                if (EXS) {
                    // half2 exp: halves MUFU count; rsum sums the STORED
                    // values so normalization stays exact by construction.
                    h01 = h2exp(__float22half2_rn(make_float2(v0, v1)));
                    h23 = h2exp(__float22half2_rn(make_float2(v2, v3)));
                    const float2 f01 = __half22float2(h01);
                    const float2 f23 = __half22float2(h23);
                    s0 += f01.x + f01.y;
                    s1 += f23.x + f23.y;
                } else {
                    h01 = __float22half2_rn(make_float2(v0, v1));
                    h23 = __float22half2_rn(make_float2(v2, v3));
                }
                *(__half2*)&zb[rl * 72 + co]       = h01;
                *(__half2*)&zb[(rl + 8) * 72 + co] = h23;
            } else {
                __half* zb = (__half*)Cg + (long)z * czs
                           + ((long)(cg / ETR) * cNK + (rg >> 6)) * (ETR * 72);
                const int rr = rg & 63;
                zb[(cg & (ETR - 1)) * 72 + rr]           = __float2half_rn(v0);
                zb[((cg + 1) & (ETR - 1)) * 72 + rr]     = __float2half_rn(v1);
                zb[(cg & (ETR - 1)) * 72 + rr + 8]       = __float2half_rn(v2);
                zb[((cg + 1) & (ETR - 1)) * 72 + rr + 8] = __float2half_rn(v3);
            }
        }
        if (EXS) {
            s0 += __shfl_xor_sync(~0u, s0, 1); s0 += __shfl_xor_sync(~0u, s0, 2);
            s1 += __shfl_xor_sync(~0u, s1, 1); s1 += __shfl_xor_sync(~0u, s1, 2);
            if (lk == 0) {
                atomicAdd(&rsum[(long)z * LL + rg], s0);
                atomicAdd(&rsum[(long)z * LL + rg + 8], s1);
            }
        }
    }
}

// ---- standalone GEMM kernels --------------------------------------------
template<int AZ, int BZ, int BROWS, int EPI, int ETR, bool EXS, bool SCL>
__global__ __launch_bounds__(256, 2)
void gemm_k(const __half* __restrict__ Apk, const __half* __restrict__ Bpk,
            void* __restrict__ Cg, float* __restrict__ rsum,
            int nkt, int cNK, long czs, long cs1, int ldc)
{
    extern __shared__ __align__(16) __half smem[];
    gemm_dev<AZ, BZ, BROWS, EPI, ETR, EXS, SCL>(
        Apk, Bpk, Cg, rsum, nkt, cNK, czs, cs1, ldc,
        blockIdx.x, blockIdx.y, blockIdx.z, gridDim.x, gridDim.y, smem);
}

// ---- fused G1 (M^T = q^T k) + G5 (Vt = x v^T) in one launch ---------------
__global__ __launch_bounds__(256, 2)
void gemm_g1g5(const __half* __restrict__ qp, const __half* __restrict__ kp,
               __half* __restrict__ Mp,
               const __half* __restrict__ xp, const __half* __restrict__ vp,
               __half* __restrict__ Vtp)
{
    extern __shared__ __align__(16) __half smem[];
    const int bid = blockIdx.x;
    if (bid < 432) {                                // G1: grid (6,6,12)
        gemm_dev<0, 0, 128, 2, 128, false, false>(
            qp, kp, Mp, nullptr, 12, 12, 6L * 12 * TH128, 0, 0,
            bid % 6, (bid / 6) % 6, bid / 36, 6, 6, smem);
    } else {                                        // G5: grid (1,8,48)
        const int t = bid - 432;
        gemm_dev<1, 2, 64, 2, 64, false, false>(
            xp, vp, Vtp, nullptr, 12, 16, 16L * TH64, 0, 0,
            0, t % 8, t / 8, 1, 8, smem);
    }
}

// ---------------------------------------------------------------------------
// Fused pack kernel: all input packing + rsum zeroing in one launch.
// ---------------------------------------------------------------------------
__device__ __forceinline__
void pack_x_dev(const float* __restrict__ x, __half* __restrict__ xp,
                int kx, int ly, int bz) {
    __half* blob = xp + (((long)bz * 8 + ly) * 12 + kx) * TH128;
    const float* src = x + ((long)(bz * LL + ly * 128)) * DD + kx * 64;
    #pragma unroll
    for (int i = 0; i < 8; i++) {
        const int s = threadIdx.x + i * 256;
        const int row = s >> 4, c4 = (s & 15) << 2;
        const float4 v = *(const float4*)&src[(long)row * DD + c4];
        *(__half2*)&blob[row * 72 + c4]     = __float22half2_rn(make_float2(v.x, v.y));
        *(__half2*)&blob[row * 72 + c4 + 2] = __float22half2_rn(make_float2(v.z, v.w));
    }
}
__device__ __forceinline__
void pack_qk_dev(const float* __restrict__ in, __half* __restrict__ op,
                 int kx, int xy, int hz) {
    __half* blob = op + (((long)hz * 6 + xy) * 12 + kx) * TH128;
    const float* src = in + ((long)hz * DD + kx * 64) * DD + xy * 128;
    #pragma unroll
    for (int i = 0; i < 8; i++) {
        const int s = threadIdx.x + i * 256;
        const int c = s >> 5, x0 = (s & 31) << 2;
        const float4 v = *(const float4*)&src[(long)c * DD + x0];
        blob[(x0 + 0) * 72 + c] = __float2half_rn(v.x);
        blob[(x0 + 1) * 72 + c] = __float2half_rn(v.y);
        blob[(x0 + 2) * 72 + c] = __float2half_rn(v.z);
        blob[(x0 + 3) * 72 + c] = __float2half_rn(v.w);
    }
}
__device__ __forceinline__
void pack_v_dev(const float* __restrict__ v, __half* __restrict__ vp,
                int kx, int hy) {
    __half* blob = vp + ((long)hy * 12 + kx) * TH64;
    const float* src = v + (long)hy * DHH * DD + kx * 64;
    #pragma unroll
    for (int i = 0; i < 4; i++) {
        const int s = threadIdx.x + i * 256;
        const int row = s >> 4, c4 = (s & 15) << 2;
        const float4 w = *(const float4*)&src[(long)row * DD + c4];
        *(__half2*)&blob[row * 72 + c4]     = __float22half2_rn(make_float2(w.x, w.y));
        *(__half2*)&blob[row * 72 + c4 + 2] = __float22half2_rn(make_float2(w.z, w.w));
    }
}

__global__ void pack_all(const float* __restrict__ x, const float* __restrict__ q,
                         const float* __restrict__ k, const float* __restrict__ v,
                         __half* __restrict__ xp, __half* __restrict__ qp,
                         __half* __restrict__ kp, __half* __restrict__ vp,
                         float* __restrict__ rsum)
{
    const int bid = blockIdx.x;
    if (bid < 384) {
        pack_x_dev(x, xp, bid % 12, (bid / 12) % 8, bid / 96);
    } else if (bid < 1248) {
        const int t = bid - 384;
        pack_qk_dev(q, qp, t % 12, (t / 12) % 6, t / 72);
    } else if (bid < 2112) {
        const int t = bid - 1248;
        pack_qk_dev(k, kp, t % 12, (t / 12) % 6, t / 72);
    } else if (bid < 2256) {
        const int t = bid - 2112;
        pack_v_dev(v, vp, t % 12, t / 12);
    } else {
        const int t = bid - 2256;                   // zero rsum: 48 x 1024 floats
        float4* dst = (float4*)&rsum[(long)t * LL];
        dst[threadIdx.x] = make_float4(0.f, 0.f, 0.f, 0.f);
    }
}

// ---------------------------------------------------------------------------
extern "C" void kernel_launch(void* const* d_in, const int* in_sizes, int n_in,
                              void* d_out, int out_size)
{
    const float* x = (const float*)d_in[0];
    const float* k = (const float*)d_in[1];
    const float* q = (const float*)d_in[2];
    const float* v = (const float*)d_in[3];
    float* out = (float*)d_out;

    __half *xp, *qp, *kp, *vp, *Mp, *Ap, *Sp, *Vtp;
    float* rs;
    cudaGetSymbolAddress((void**)&xp, g_xp);
    cudaGetSymbolAddress((void**)&qp, g_qp);
    cudaGetSymbolAddress((void**)&kp, g_kp);
    cudaGetSymbolAddress((void**)&vp, g_vp);
    cudaGetSymbolAddress((void**)&Mp, g_Mp);
    cudaGetSymbolAddress((void**)&Ap, g_Ap);
    cudaGetSymbolAddress((void**)&Sp, g_Sp);
    cudaGetSymbolAddress((void**)&Vtp, g_Vtp);
    cudaGetSymbolAddress((void**)&rs, g_rsum);

    const int SM128 = 1024 + 3 * (18432 + 18432);   // 111616
    const int SM64  = 1024 + 3 * (18432 + 9216);    // 83968

    auto* G2 = gemm_k<1, 2, 128, 1, 0, false, false>;
    auto* G3 = gemm_k<0, 1, 128, 1, 0, true, false>;
    auto* G6 = gemm_k<0, 0, 64, 0, 0, false, true>;
    cudaFuncSetAttribute(gemm_g1g5, cudaFuncAttributeMaxDynamicSharedMemorySize, SM128);
    cudaFuncSetAttribute(G2, cudaFuncAttributeMaxDynamicSharedMemorySize, SM128);
    cudaFuncSetAttribute(G3, cudaFuncAttributeMaxDynamicSharedMemorySize, SM128);
    cudaFuncSetAttribute(G6, cudaFuncAttributeMaxDynamicSharedMemorySize, SM64);

    // 0) pack inputs + zero rsum, one launch
    pack_all<<<dim3(2304), 256>>>(x, q, k, v, xp, qp, kp, vp, rs);

    // 1+5) M^T = q^T k  and  Vt = x v^T, one launch
    gemm_g1g5<<<dim3(816), 256, SM128>>>(qp, kp, Mp, xp, vp, Vtp);

    // 2) A[l,e] = sum_d x[l,d] M^T[e,d]
    G2<<<dim3(6, 8, BB * HH), 256, SM128>>>(xp, Mp, Ap, rs, 12, 12, 8L * 12 * TH128, 0, 0);

    // 3) P[l,m] = exp(sum_e A[l,e] x[m,e]); rsum[l] += row sums (atomic)
    G3<<<dim3(8, 8, BB * HH), 256, SM128>>>(Ap, xp, Sp, rs, 12, 16, 8L * 16 * TH128, 0, 0);

    // 6) out[l, h*64+j] = (sum_m P[l,m] Vt[j,m]) / rsum[l]
    G6<<<dim3(1, 8, BB * HH), 256, SM64>>>(Sp, Vtp, out, rs, 16, 0, 0, (long)LL * DD, DD);
}